// round 16
// baseline (speedup 1.0000x reference)
#include <cuda_runtime.h>
#include <math.h>

// Problem dims
#define H  8
#define NN 8
#define D  512
#define C  64
#define C2 32
#define I  96
#define SCALE (1.0f/24.0f)   // 1/sqrt(576)

// Output packing (T, M, P, w), float32
#define SZ_T  (NN*C*I*I)
#define OFF_T 0
#define OFF_M (OFF_T + SZ_T)
#define SZ_M  (NN*H*C2)
#define OFF_P (OFF_M + SZ_M)
#define SZ_P  (NN*H*C*I*I)
#define OFF_W (OFF_P + SZ_P)

// ---------------- scratch ----------------
__device__ __align__(16) float g_M  [NN*H*C2];
__device__ __align__(16) float g_Av [NN*H*C];
__device__ __align__(16) float g_Bxk[H*C*I];
__device__ __align__(16) float g_Byk[H*C*I];
__device__ __align__(16) float g_Vx [H*C*I];
__device__ __align__(16) float g_Vy [H*C*I];
__device__ __align__(16) float g_S2 [9*C*C];
__device__ __align__(16) float g_Cs [NN*H*C*9];
__device__ __align__(16) float g_Gx [H*C*3*I];
__device__ __align__(16) float g_Gy [H*C*3*I];

// ============================================================================
// k_A1: y = X@lw^T + lb -> BN over n -> ReLU -> g_M, out.M   (256 blocks)
// ============================================================================
__global__ void __launch_bounds__(256) k_A1(
    const float* __restrict__ X,  const float* __restrict__ lw,
    const float* __restrict__ lb, const float* __restrict__ gamma,
    const float* __restrict__ beta, float* __restrict__ out)
{
    __shared__ float red[64];
    __shared__ float sy[NN];
    int b = blockIdx.x;
    int t = threadIdx.x;
    int h = b >> 5, c2 = b & 31;
    int wid = t >> 5, lane = t & 31;
    float part[NN];
#pragma unroll
    for (int n = 0; n < NN; n++) part[n] = 0.f;
#pragma unroll
    for (int it = 0; it < 2; it++) {
        int d = t + it*256;
        float w = lw[(h*C2 + c2)*D + d];
#pragma unroll
        for (int n = 0; n < NN; n++) part[n] += w * X[(h*NN + n)*D + d];
    }
#pragma unroll
    for (int off = 16; off; off >>= 1) {
#pragma unroll
        for (int n = 0; n < NN; n++)
            part[n] += __shfl_down_sync(0xffffffffu, part[n], off);
    }
    if (lane == 0) {
#pragma unroll
        for (int n = 0; n < NN; n++) red[wid*NN + n] = part[n];
    }
    __syncthreads();
    if (t < NN) {
        float y = lb[h*C2 + c2];
#pragma unroll
        for (int w = 0; w < 8; w++) y += red[w*NN + t];
        sy[t] = y;
    }
    __syncthreads();
    if (t < NN) {
        float mu = 0.f;
#pragma unroll
        for (int k = 0; k < NN; k++) mu += sy[k];
        mu *= (1.0f/NN);
        float m2 = 0.f;
#pragma unroll
        for (int k = 0; k < NN; k++) { float v = sy[k] - mu; m2 += v*v; }
        float var = m2 * (1.0f/NN);
        float m = (sy[t] - mu) * rsqrtf(var + 1e-5f) * gamma[h*C2 + c2] + beta[h*C2 + c2];
        m = fmaxf(m, 0.f);
        g_M[(t*H + h)*C2 + c2] = m;
        out[OFF_M + (t*H + h)*C2 + c2] = m;
    }
}

// ============================================================================
// k_P: P writer (forked stream) — 151 MB of broadcast stores. 512 blocks, 96 thr
// ============================================================================
__global__ void __launch_bounds__(96) k_P(const float* __restrict__ px,
                                          const float* __restrict__ py,
                                          float* __restrict__ out) {
    int b2 = blockIdx.x;                // (n, c)
    int c = b2 & 63, n = b2 >> 6;
    int t = threadIdx.x;
    int j4 = t % 24, hh = t / 24;       // hh in [0,4); handles h = hh, hh+4
    int jj0 = j4 * 4;
    if (c < C2) {
        const float4 p4 = *(const float4*)(px + c*I + jj0);
#pragma unroll
        for (int g = 0; g < 2; g++) {
            int h = hh + g*4;
            float m = g_M[(n*H + h)*C2 + c];
            float4 pv = make_float4(m + p4.x, m + p4.y, m + p4.z, m + p4.w);
            float* dst = out + OFF_P + (size_t)((n*H + h)*C + c)*I*I + jj0;
#pragma unroll 4
            for (int ii = 0; ii < I; ii++)
                __stcs((float4*)(dst + ii*I), pv);
        }
    } else {
        int c2 = c - C2;
        float m0 = g_M[(n*H + hh)*C2 + c2];
        float m1 = g_M[(n*H + hh + 4)*C2 + c2];
        float* d0 = out + OFF_P + (size_t)((n*H + hh)*C + c)*I*I + jj0;
        float* d1 = out + OFF_P + (size_t)((n*H + hh + 4)*C + c)*I*I + jj0;
#pragma unroll 4
        for (int ii = 0; ii < I; ii++) {
            float pyv = __ldg(py + c2*I + ii);
            float v0 = m0 + pyv, v1 = m1 + pyv;
            __stcs((float4*)(d0 + ii*I), make_float4(v0, v0, v0, v0));
            __stcs((float4*)(d1 + ii*I), make_float4(v1, v1, v1, v1));
        }
    }
}

// ============================================================================
// k_A2: input-only tables (runs concurrent with k_P):
//   [0,512)   : Bxk/Byk/Vx/Vy 1D fields
//   [512,576) : S2 border-sum tables
// 96 threads
// ============================================================================
__global__ void __launch_bounds__(96) k_A2(
    const float* __restrict__ px, const float* __restrict__ py,
    const float* __restrict__ kw, const float* __restrict__ vw,
    const float* __restrict__ sw)
{
    int b = blockIdx.x;
    int t = threadIdx.x;
    if (b < 512) {
        int h = b >> 6; (void)h;
        int p = t;
        const float* kwr = kw + b*C;
        const float* vwr = vw + b*C;
        float bx = 0.f, by = 0.f, vx = 0.f, vy = 0.f;
#pragma unroll 8
        for (int c2 = 0; c2 < C2; c2++) {
            float pxv = px[c2*I + p];
            float pyv = py[c2*I + p];
            bx += kwr[c2]      * pxv;
            by += kwr[c2 + C2] * pyv;
            vx += vwr[c2]      * pxv;
            vy += vwr[c2 + C2] * pyv;
        }
        g_Bxk[b*I + p] = bx;
        g_Byk[b*I + p] = by;
        g_Vx [b*I + p] = vx;
        g_Vy [b*I + p] = vy;
    } else {
        if (t >= C) return;
        int o = b - 512, c = t;
        float s[9];
        const float* p = sw + (o*C + c)*9;
#pragma unroll
        for (int k = 0; k < 9; k++) s[k] = p[k];
#pragma unroll
        for (int vy = 0; vy < 3; vy++) {
#pragma unroll
            for (int vx = 0; vx < 3; vx++) {
                float acc = 0.f;
#pragma unroll
                for (int ky = 0; ky < 3; ky++) {
                    if (vy == 0 && ky == 0) continue;
                    if (vy == 2 && ky == 2) continue;
#pragma unroll
                    for (int kx = 0; kx < 3; kx++) {
                        if (vx == 0 && kx == 0) continue;
                        if (vx == 2 && kx == 2) continue;
                        acc += s[ky*3 + kx];
                    }
                }
                g_S2[((vy*3 + vx)*C + c)*C + o] = acc;
            }
        }
    }
}

// ============================================================================
// k_B2 (runs concurrent with k_P):
//   [0,64)    : A_k/A_v + Cs (fused through smem)
//   [64,3136) : Gx / Gy 1D conv tables
// 96 threads
// ============================================================================
__global__ void __launch_bounds__(96) k_B2(
    const float* __restrict__ kw, const float* __restrict__ kb,
    const float* __restrict__ vw, const float* __restrict__ vb,
    const float* __restrict__ sw, const float* __restrict__ sb)
{
    int b = blockIdx.x;
    int t = threadIdx.x;

    if (b < 64) {
        __shared__ float sAk[C];
        int n = b >> 3, h = b & 7;
        if (t < C) {
            int d = t;
            const float* kwr = kw + (h*C + d)*C;
            const float* vwr = vw + (h*C + d)*C;
            const float* mr  = g_M + (n*H + h)*C2;
            float ak = 0.f, av = 0.f;
#pragma unroll
            for (int c2 = 0; c2 < C2; c2++) {
                float m = mr[c2];
                ak += (kwr[c2] + kwr[c2 + C2]) * m;
                av += (vwr[c2] + vwr[c2 + C2]) * m;
            }
            g_Av[(n*H + h)*C + d] = av + vb[h*C + d];
            sAk[d] = ak + kb[h*C + d];
        }
        __syncthreads();
        if (t < C) {
            int o = t;
            float sbv = sb[o];
#pragma unroll
            for (int v = 0; v < 9; v++) {
                float acc = 0.f;
#pragma unroll 8
                for (int c = 0; c < C; c++)
                    acc += sAk[c] * g_S2[(v*C + c)*C + o];
                g_Cs[((n*H + h)*C + o)*9 + v] = (acc + sbv) * SCALE;
            }
        }
    } else {
        int b2 = b - 64;
        int v   = b2 % 3;
        int o   = (b2/3) % C;
        int h   = (b2/(3*C)) % H;
        int tab = b2 / (3*C*H);
        int p = t;
        __shared__ float cs[C*3];
        for (int q = p; q < C*3; q += 96) {
            int c = q/3, k = q%3;
            float acc = 0.f;
#pragma unroll
            for (int qq = 0; qq < 3; qq++) {
                if (v == 0 && qq == 0) continue;
                if (v == 2 && qq == 2) continue;
                acc += (tab == 0) ? sw[(o*C + c)*9 + qq*3 + k]
                                  : sw[(o*C + c)*9 + k*3 + qq];
            }
            cs[q] = acc;
        }
        __syncthreads();
        const float* src = (tab == 0) ? (g_Bxk + h*C*I) : (g_Byk + h*C*I);
        float val = 0.f;
#pragma unroll
        for (int k = 0; k < 3; k++) {
            int q = p + k - 1;
            if (q < 0 || q >= I) continue;
            for (int c = 0; c < C; c++)
                val += cs[c*3 + k] * src[c*I + q];
        }
        float* dst = (tab == 0) ? g_Gy : g_Gx;
        dst = (tab == 0) ? g_Gx : g_Gy;
        dst[((h*C + o)*3 + v)*I + p] = val * SCALE;
    }
}

// ============================================================================
// k_WT: softmax w (189 MB... 170 MB w+T stores), runs concurrent with k_P.
// grid (24, 64, 8), 96 threads
// ============================================================================
__global__ void __launch_bounds__(96) k_WT(float* __restrict__ out) {
    __shared__ float sGx[H][I];    // vy = 1 slice
    __shared__ float sVx[H][I];
    __shared__ float sBase[32], sE0[32], sE2[32], sVb[32];

    int t = threadIdx.x;
    int bx = blockIdx.x, c = blockIdx.y, n = blockIdx.z;

    if (t < 32) {
        int h = t >> 2, il = t & 3;
        int ii = bx*4 + il;
        int vy = (ii == 0) ? 0 : (ii == (I-1) ? 2 : 1);
        const float* cs = g_Cs + ((n*H + h)*C + c)*9 + vy*3;
        const float* gy = g_Gy + (h*C + c)*3*I;
        sBase[t] = cs[1] + gy[I + ii];
        sE0[t]   = cs[0] + gy[ii];
        sE2[t]   = cs[2] + gy[2*I + ii];
        sVb[t]   = g_Av[(n*H + h)*C + c] + g_Vy[(h*C + c)*I + ii];
    }
#pragma unroll
    for (int q = t; q < 2*I; q += 96) {     // 192 float4 slots = 8h x 24
        int h = q / 24, j4 = q % 24;
        *(float4*)&sGx[h][j4*4] = *(const float4*)(g_Gx + ((h*C + c)*3 + 1)*I + j4*4);
        *(float4*)&sVx[h][j4*4] = *(const float4*)(g_Vx + (h*C + c)*I + j4*4);
    }
    __syncthreads();

    int j4 = t % 24, il = t / 24;
    int ii = bx*4 + il, jj0 = j4*4;
    int vy = (ii == 0) ? 0 : (ii == (I-1) ? 2 : 1);
    int hb = il;

    float s[H][4];
    float mx0 = -1e30f, mx1 = -1e30f, mx2 = -1e30f, mx3 = -1e30f;
#pragma unroll
    for (int h = 0; h < H; h++) {
        float4 gx = (vy == 1) ? *(const float4*)&sGx[h][jj0]
                              : *(const float4*)(g_Gx + ((h*C + c)*3 + vy)*I + jj0);
        float base = sBase[h*4 + hb];
        float s0 = base + gx.x, s1 = base + gx.y, s2 = base + gx.z, s3 = base + gx.w;
        if (jj0 == 0)     s0 = sE0[h*4 + hb] + gx.x;
        if (jj0 == I - 4) s3 = sE2[h*4 + hb] + gx.w;
        s[h][0] = s0; s[h][1] = s1; s[h][2] = s2; s[h][3] = s3;
        mx0 = fmaxf(mx0, s0); mx1 = fmaxf(mx1, s1);
        mx2 = fmaxf(mx2, s2); mx3 = fmaxf(mx3, s3);
    }
    float sum0 = 0.f, sum1 = 0.f, sum2 = 0.f, sum3 = 0.f;
#pragma unroll
    for (int h = 0; h < H; h++) {
        s[h][0] = __expf(s[h][0] - mx0); sum0 += s[h][0];
        s[h][1] = __expf(s[h][1] - mx1); sum1 += s[h][1];
        s[h][2] = __expf(s[h][2] - mx2); sum2 += s[h][2];
        s[h][3] = __expf(s[h][3] - mx3); sum3 += s[h][3];
    }
    float i0 = __fdividef(1.f, sum0), i1 = __fdividef(1.f, sum1);
    float i2 = __fdividef(1.f, sum2), i3 = __fdividef(1.f, sum3);

    float4 acc = make_float4(0.f, 0.f, 0.f, 0.f);
    int pixbase = ii*I + jj0;
#pragma unroll
    for (int h = 0; h < H; h++) {
        float w0 = s[h][0]*i0, w1 = s[h][1]*i1, w2 = s[h][2]*i2, w3 = s[h][3]*i3;
        size_t idx = (size_t)((n*H + h)*C + c)*I*I + pixbase;
        __stcs((float4*)(out + OFF_W + idx), make_float4(w0, w1, w2, w3));

        float vbv = sVb[h*4 + hb];
        const float4 vx4 = *(const float4*)&sVx[h][jj0];
        acc.x += w0*(vbv + vx4.x);
        acc.y += w1*(vbv + vx4.y);
        acc.z += w2*(vbv + vx4.z);
        acc.w += w3*(vbv + vx4.w);
    }
    __stcs((float4*)(out + OFF_T + (size_t)(n*C + c)*I*I + pixbase), acc);
}

// ---------------- launch ----------------
extern "C" void kernel_launch(void* const* d_in, const int* in_sizes, int n_in,
                              void* d_out, int out_size) {
    (void)in_sizes; (void)n_in; (void)out_size;
    const float* X     = (const float*)d_in[0];
    const float* lin_w = (const float*)d_in[1];
    const float* lin_b = (const float*)d_in[2];
    const float* gamma = (const float*)d_in[3];
    const float* beta  = (const float*)d_in[4];
    const float* px    = (const float*)d_in[5];
    const float* py    = (const float*)d_in[6];
    const float* kw    = (const float*)d_in[7];
    const float* kb    = (const float*)d_in[8];
    const float* vw    = (const float*)d_in[9];
    const float* vb    = (const float*)d_in[10];
    const float* sw    = (const float*)d_in[11];
    const float* sb    = (const float*)d_in[12];
    float* out = (float*)d_out;

    // Lazily-created side stream + events (first call is the uncaptured
    // correctness run; capture reuses them). Only launches + event ops are
    // issued per call — fully graph-capturable, no allocation.
    static cudaStream_t s_p = nullptr;
    static cudaEvent_t ev_m = nullptr, ev_p = nullptr;
    if (s_p == nullptr) {
        cudaStreamCreateWithFlags(&s_p, cudaStreamNonBlocking);
        cudaEventCreateWithFlags(&ev_m, cudaEventDisableTiming);
        cudaEventCreateWithFlags(&ev_p, cudaEventDisableTiming);
    }

    // main stream: minimal producer of g_M
    k_A1<<<256, 256>>>(X, lin_w, lin_b, gamma, beta, out);
    cudaEventRecord(ev_m, 0);

    // fork: P writer (151 MB) overlaps all remaining setup + WT
    cudaStreamWaitEvent(s_p, ev_m, 0);
    k_P<<<512, 96, 0, s_p>>>(px, py, out);
    cudaEventRecord(ev_p, s_p);

    // main stream: rest of setup, then w+T writer
    k_A2<<<576, 96>>>(px, py, kw, vw, sw);
    k_B2<<<3136, 96>>>(kw, kb, vw, vb, sw, sb);
    k_WT<<<dim3(I/4, C, NN), 96>>>(out);

    // join P before capture end
    cudaStreamWaitEvent(0, ev_p, 0);
}